// round 2
// baseline (speedup 1.0000x reference)
#include <cuda_runtime.h>
#include <cuda_bf16.h>
#include <math.h>

// Problem constants
#define B_   64
#define P_   196
#define ENC_ 2048
#define H_   512
#define E_   512
#define A_   512
#define V_   30000
#define T_   20
#define GH_  2048   // 4*H
#define KCAT 3072   // E + ENC + H  (fused gates GEMM K)

// ---------------- scratch (static device memory; allocation-free) ----------------
__device__ __align__(16) float g_att_enc[B_ * P_ * A_];   // [B,P,A]  ~25.7 MB
__device__ __align__(16) float g_att_h [B_ * A_];
__device__ __align__(16) float g_scores[B_ * P_];
__device__ __align__(16) float g_alpha [B_ * P_];
__device__ __align__(16) float g_weighted[B_ * ENC_];
__device__ __align__(16) float g_sh   [B_ * H_];
__device__ __align__(16) float g_gate [B_ * ENC_];
__device__ __align__(16) float g_inp  [B_ * KCAT];
__device__ __align__(16) float g_gates[B_ * GH_];
__device__ __align__(16) float g_h    [B_ * H_];
__device__ __align__(16) float g_c    [B_ * H_];
__device__ __align__(16) float g_mean [B_ * ENC_];
__device__ __align__(16) float g_Wcat [GH_ * KCAT];       // [4H, E+ENC+H] ~25 MB
__device__ __align__(16) float g_bcat [GH_];
__device__ int g_tok64;

__device__ __forceinline__ float sigf(float x) { return 1.f / (1.f + __expf(-x)); }

// ---------------- generic SGEMM: C[M,N] = A[M,K] * B[N,K]^T ----------------
// mode 0: C = acc + bias (blockIdx.z must be 1 chunk)
// mode 1: atomicAdd(C, acc)  (C pre-initialized with bias; split-K via blockIdx.z)
#define BM 64
#define BN 64
#define BK 16

__global__ __launch_bounds__(256)
void sgemm_kernel(const float* __restrict__ Amat, const float* __restrict__ Bmat,
                  float* __restrict__ C, const float* __restrict__ bias,
                  int M, int N, int K, int ldc, int kchunk, int mode)
{
    __shared__ float As[BK][BM + 4];
    __shared__ float Bs[BK][BN + 4];

    const int tid = threadIdx.x;
    const int tx = tid & 15;          // n subtile
    const int ty = tid >> 4;          // m subtile
    const int m0 = blockIdx.y * BM;
    const int n0 = blockIdx.x * BN;

    const int kbeg = blockIdx.z * kchunk;
    const int kend = kbeg + kchunk;

    const int lr = tid >> 2;          // 0..63  (tile row)
    const int lc = (tid & 3) << 2;    // 0,4,8,12 (tile k, float4)

    float acc[4][4] = {};

    for (int k0 = kbeg; k0 < kend; k0 += BK) {
        float4 a4 = make_float4(0.f, 0.f, 0.f, 0.f);
        int am = m0 + lr;
        if (am < M) a4 = *(const float4*)(Amat + (size_t)am * K + k0 + lc);
        As[lc + 0][lr] = a4.x; As[lc + 1][lr] = a4.y;
        As[lc + 2][lr] = a4.z; As[lc + 3][lr] = a4.w;

        float4 b4 = make_float4(0.f, 0.f, 0.f, 0.f);
        int bn = n0 + lr;
        if (bn < N) b4 = *(const float4*)(Bmat + (size_t)bn * K + k0 + lc);
        Bs[lc + 0][lr] = b4.x; Bs[lc + 1][lr] = b4.y;
        Bs[lc + 2][lr] = b4.z; Bs[lc + 3][lr] = b4.w;

        __syncthreads();
#pragma unroll
        for (int k = 0; k < BK; ++k) {
            float4 ra = *(const float4*)&As[k][ty << 2];
            float4 rb = *(const float4*)&Bs[k][tx << 2];
            acc[0][0] += ra.x * rb.x; acc[0][1] += ra.x * rb.y;
            acc[0][2] += ra.x * rb.z; acc[0][3] += ra.x * rb.w;
            acc[1][0] += ra.y * rb.x; acc[1][1] += ra.y * rb.y;
            acc[1][2] += ra.y * rb.z; acc[1][3] += ra.y * rb.w;
            acc[2][0] += ra.z * rb.x; acc[2][1] += ra.z * rb.y;
            acc[2][2] += ra.z * rb.z; acc[2][3] += ra.z * rb.w;
            acc[3][0] += ra.w * rb.x; acc[3][1] += ra.w * rb.y;
            acc[3][2] += ra.w * rb.z; acc[3][3] += ra.w * rb.w;
        }
        __syncthreads();
    }

#pragma unroll
    for (int i = 0; i < 4; ++i) {
        int m = m0 + (ty << 2) + i;
        if (m >= M) continue;
#pragma unroll
        for (int j = 0; j < 4; ++j) {
            int n = n0 + (tx << 2) + j;
            if (n >= N) continue;
            if (mode == 0) {
                float v = acc[i][j] + (bias ? bias[n] : 0.f);
                C[(size_t)m * ldc + n] = v;
            } else {
                atomicAdd(&C[(size_t)m * ldc + n], acc[i][j]);
            }
        }
    }
}

// ---------------- small custom kernels ----------------

// detect whether captions buffer is int64 (odd int32 words of first B*T words all zero)
__global__ __launch_bounds__(256) void detect_tok_kernel(const int* __restrict__ cap32)
{
    __shared__ int bad;
    if (threadIdx.x == 0) bad = 0;
    __syncthreads();
    for (int i = 2 * threadIdx.x + 1; i < B_ * T_; i += 2 * blockDim.x)
        if (cap32[i] != 0) bad = 1;
    __syncthreads();
    if (threadIdx.x == 0) g_tok64 = bad ? 0 : 1;
}

// zero the final [B,1,V] output slice
__global__ __launch_bounds__(256) void zero_last_kernel(float* __restrict__ out)
{
    int idx = blockIdx.x * blockDim.x + threadIdx.x;
    if (idx >= B_ * V_) return;
    int b = idx / V_, v = idx % V_;
    out[(size_t)b * T_ * V_ + (size_t)(T_ - 1) * V_ + v] = 0.f;
}

// mean over P
__global__ __launch_bounds__(256) void mean_enc_kernel(const float* __restrict__ enc)
{
    int b = blockIdx.y;
    int e = blockIdx.x * 256 + threadIdx.x;
    float s = 0.f;
    const float* base = enc + (size_t)b * P_ * ENC_ + e;
    for (int p = 0; p < P_; ++p) s += base[(size_t)p * ENC_];
    g_mean[b * ENC_ + e] = s * (1.f / (float)P_);
}

// fused weight [W_ih | W_hh] and bias (b_ih + b_hh)
__global__ __launch_bounds__(256)
void build_wcat_kernel(const float* __restrict__ W_ih, const float* __restrict__ W_hh,
                       const float* __restrict__ b_ih, const float* __restrict__ b_hh)
{
    int idx = blockIdx.x * blockDim.x + threadIdx.x;
    if (idx < GH_) g_bcat[idx] = b_ih[idx] + b_hh[idx];
    if (idx >= GH_ * KCAT) return;
    int n = idx / KCAT, j = idx % KCAT;
    g_Wcat[idx] = (j < E_ + ENC_) ? W_ih[(size_t)n * (E_ + ENC_) + j]
                                  : W_hh[(size_t)n * H_ + (j - E_ - ENC_)];
}

// h = bch, c = bcc  (bias init before split-K GEMM)
__global__ __launch_bounds__(256)
void init_h0c0_kernel(const float* __restrict__ bch, const float* __restrict__ bcc)
{
    int idx = blockIdx.x * blockDim.x + threadIdx.x;
    if (idx >= B_ * H_) return;
    int n = idx % H_;
    g_h[idx] = bch[n];
    g_c[idx] = bcc[n];
}

__global__ __launch_bounds__(256) void sh0_kernel()
{
    int idx = blockIdx.x * blockDim.x + threadIdx.x;
    if (idx < B_ * H_) g_sh[idx] = sigf(g_h[idx]);
}

// per-step bias init for att_h (bh), gate (bg), gates (bcat)
__global__ __launch_bounds__(256)
void init3_kernel(const float* __restrict__ bh, const float* __restrict__ bg)
{
    int idx = blockIdx.x * blockDim.x + threadIdx.x;
    if (idx < B_ * A_) {
        g_att_h[idx] = bh[idx % A_];
    }
    int i2 = idx - B_ * A_;
    if (i2 >= 0 && i2 < B_ * ENC_) g_gate[i2] = bg[i2 % ENC_];
    int i3 = idx - B_ * A_ - B_ * ENC_;
    if (i3 >= 0 && i3 < B_ * GH_) g_gates[i3] = g_bcat[i3 % GH_];
}

// scores[b,p] = sum_a relu(att_enc[b,p,a] + att_h[b,a]) * Wa[a] + ba
__global__ __launch_bounds__(256)
void scores_kernel(const float* __restrict__ Wa, const float* __restrict__ ba)
{
    __shared__ float s_h[A_];
    __shared__ float s_w[A_];
    int b = blockIdx.y;
    for (int i = threadIdx.x; i < A_; i += 256) {
        s_h[i] = g_att_h[b * A_ + i];
        s_w[i] = Wa[i];
    }
    __syncthreads();
    int w = threadIdx.x >> 5, lane = threadIdx.x & 31;
    int p = blockIdx.x * 8 + w;
    if (p >= P_) return;
    const float* row = g_att_enc + ((size_t)(b * P_ + p)) * A_;
    float s = 0.f;
    for (int a = lane; a < A_; a += 32) {
        float v = row[a] + s_h[a];
        s += fmaxf(v, 0.f) * s_w[a];
    }
#pragma unroll
    for (int o = 16; o; o >>= 1) s += __shfl_xor_sync(0xffffffff, s, o);
    if (lane == 0) g_scores[b * P_ + p] = s + ba[0];
}

__global__ __launch_bounds__(256) void softmax_kernel()
{
    __shared__ float red[256];
    int b = blockIdx.x, t = threadIdx.x;
    float v = (t < P_) ? g_scores[b * P_ + t] : -1e30f;
    red[t] = v; __syncthreads();
    for (int s = 128; s; s >>= 1) { if (t < s) red[t] = fmaxf(red[t], red[t + s]); __syncthreads(); }
    float mx = red[0]; __syncthreads();
    float e = (t < P_) ? __expf(v - mx) : 0.f;
    red[t] = e; __syncthreads();
    for (int s = 128; s; s >>= 1) { if (t < s) red[t] += red[t + s]; __syncthreads(); }
    float inv = 1.f / red[0];
    if (t < P_) g_alpha[b * P_ + t] = e * inv;
}

// weighted[b,e] = sum_p alpha[b,p] * enc[b,p,e]
__global__ __launch_bounds__(256) void weighted_kernel(const float* __restrict__ enc)
{
    __shared__ float sa[P_];
    int b = blockIdx.y;
    int e = blockIdx.x * 256 + threadIdx.x;
    for (int i = threadIdx.x; i < P_; i += 256) sa[i] = g_alpha[b * P_ + i];
    __syncthreads();
    const float* base = enc + (size_t)b * P_ * ENC_ + e;
    float s = 0.f;
    for (int p = 0; p < P_; ++p) s += sa[p] * base[(size_t)p * ENC_];
    g_weighted[b * ENC_ + e] = s;
}

// inp = [x_t, weighted*gate, h]
__global__ __launch_bounds__(256)
void build_inp_kernel(const void* __restrict__ cap, const float* __restrict__ emb, int t)
{
    int idx = blockIdx.x * blockDim.x + threadIdx.x;
    if (idx >= B_ * KCAT) return;
    int b = idx / KCAT, j = idx % KCAT;
    float v;
    if (j < E_) {
        long long tok = g_tok64 ? ((const long long*)cap)[b * T_ + t]
                                : (long long)((const int*)cap)[b * T_ + t];
        v = emb[(size_t)tok * E_ + j];
    } else if (j < E_ + ENC_) {
        int e = j - E_;
        v = g_weighted[b * ENC_ + e] * g_gate[b * ENC_ + e];
    } else {
        v = g_h[b * H_ + (j - E_ - ENC_)];
    }
    g_inp[idx] = v;
}

// LSTM pointwise: update c,h, emit sigmoid(h) for next step's gate
__global__ __launch_bounds__(256) void lstm_kernel()
{
    int idx = blockIdx.x * blockDim.x + threadIdx.x;
    if (idx >= B_ * H_) return;
    int b = idx / H_, j = idx % H_;
    const float* g = g_gates + (size_t)b * GH_;
    float i_ = sigf(g[j]);
    float f_ = sigf(g[H_ + j]);
    float gg = tanhf(g[2 * H_ + j]);
    float o_ = sigf(g[3 * H_ + j]);
    float c = f_ * g_c[idx] + i_ * gg;
    float h = o_ * tanhf(c);
    g_c[idx] = c;
    g_h[idx] = h;
    g_sh[idx] = sigf(h);
}

// ---------------- host orchestration ----------------
static inline float* sym(const void* s)
{
    void* p = nullptr;
    cudaGetSymbolAddress(&p, s);
    return (float*)p;
}

extern "C" void kernel_launch(void* const* d_in, const int* in_sizes, int n_in,
                              void* d_out, int out_size)
{
    const float* encode_out = (const float*)d_in[0];
    const void*  captions   = d_in[1];
    const float* emb        = (const float*)d_in[2];
    const float* W_ih       = (const float*)d_in[3];
    const float* b_ih       = (const float*)d_in[4];
    const float* W_hh       = (const float*)d_in[5];
    const float* b_hh       = (const float*)d_in[6];
    const float* We         = (const float*)d_in[7];
    const float* be         = (const float*)d_in[8];
    const float* Wh         = (const float*)d_in[9];
    const float* bh         = (const float*)d_in[10];
    const float* Wa         = (const float*)d_in[11];
    const float* ba         = (const float*)d_in[12];
    const float* Wch        = (const float*)d_in[13];
    const float* bch        = (const float*)d_in[14];
    const float* Wcc        = (const float*)d_in[15];
    const float* bcc        = (const float*)d_in[16];
    const float* Wfc        = (const float*)d_in[17];
    const float* bfc        = (const float*)d_in[18];
    const float* Wg         = (const float*)d_in[19];
    const float* bg         = (const float*)d_in[20];
    float* out = (float*)d_out;

    float* p_att_enc = sym(g_att_enc);
    float* p_att_h   = sym(g_att_h);
    float* p_sh      = sym(g_sh);
    float* p_gate    = sym(g_gate);
    float* p_inp     = sym(g_inp);
    float* p_gates   = sym(g_gates);
    float* p_h       = sym(g_h);
    float* p_c       = sym(g_c);
    float* p_mean    = sym(g_mean);
    float* p_Wcat    = sym(g_Wcat);

    // ---- prologue ----
    detect_tok_kernel<<<1, 256>>>((const int*)captions);
    zero_last_kernel<<<(B_ * V_ + 255) / 256, 256>>>(out);
    mean_enc_kernel<<<dim3(ENC_ / 256, B_), 256>>>(encode_out);
    build_wcat_kernel<<<(GH_ * KCAT + 255) / 256, 256>>>(W_ih, W_hh, b_ih, b_hh);
    init_h0c0_kernel<<<(B_ * H_ + 255) / 256, 256>>>(bch, bcc);
    // h0 = mean @ Wch^T (+bch via init), split-K 8
    sgemm_kernel<<<dim3(H_ / BN, 1, 8), 256>>>(p_mean, Wch, p_h, nullptr,
                                               B_, H_, ENC_, H_, ENC_ / 8, 1);
    sgemm_kernel<<<dim3(H_ / BN, 1, 8), 256>>>(p_mean, Wcc, p_c, nullptr,
                                               B_, H_, ENC_, H_, ENC_ / 8, 1);
    sh0_kernel<<<(B_ * H_ + 255) / 256, 256>>>();
    // att_enc = encode_out @ We^T + be  (M = B*P)
    sgemm_kernel<<<dim3(A_ / BN, (B_ * P_) / BM, 1), 256>>>(encode_out, We, p_att_enc, be,
                                                            B_ * P_, A_, ENC_, A_, ENC_, 0);

    const int INIT3_N = B_ * A_ + B_ * ENC_ + B_ * GH_;

    // ---- timesteps ----
    for (int t = 0; t < T_ - 1; ++t) {
        init3_kernel<<<(INIT3_N + 255) / 256, 256>>>(bh, bg);
        // att_h = h @ Wh^T (+bh)
        sgemm_kernel<<<dim3(A_ / BN, 1, 8), 256>>>(p_h, Wh, p_att_h, nullptr,
                                                   B_, A_, H_, A_, H_ / 8, 1);
        scores_kernel<<<dim3((P_ + 7) / 8, B_), 256>>>(Wa, ba);
        softmax_kernel<<<B_, 256>>>();
        weighted_kernel<<<dim3(ENC_ / 256, B_), 256>>>(encode_out);
        // gate = sigmoid(h) @ Wg^T (+bg)
        sgemm_kernel<<<dim3(ENC_ / BN, 1, 4), 256>>>(p_sh, Wg, p_gate, nullptr,
                                                     B_, ENC_, H_, ENC_, H_ / 4, 1);
        build_inp_kernel<<<(B_ * KCAT + 255) / 256, 256>>>(captions, emb, t);
        // gates = inp @ Wcat^T (+b_ih+b_hh)
        sgemm_kernel<<<dim3(GH_ / BN, 1, 8), 256>>>(p_inp, p_Wcat, p_gates, nullptr,
                                                    B_, GH_, KCAT, GH_, KCAT / 8, 1);
        lstm_kernel<<<(B_ * H_ + 255) / 256, 256>>>();
        // pred = h_new @ Wfc^T + bfc  -> out[:, t, :]
        sgemm_kernel<<<dim3((V_ + BN - 1) / BN, 1, 1), 256>>>(p_h, Wfc, out + (size_t)t * V_, bfc,
                                                              B_, V_, H_, T_ * V_, H_, 0);
    }
}

// round 6
// speedup vs baseline: 2.3269x; 2.3269x over previous
#include <cuda_runtime.h>
#include <cuda_bf16.h>
#include <math.h>
#include <stdint.h>

// Problem constants
#define B_   64
#define P_   196
#define ENC_ 2048
#define H_   512
#define E_   512
#define A_   512
#define V_   30000
#define T_   20
#define GH_  2048   // 4*H
#define KCAT 3072   // E + ENC + H  (fused gates GEMM K)
#define MPRED (19 * B_)  // 1216 rows of batched pred GEMM

// ---------------- scratch (static device memory; allocation-free) ----------------
__device__ __align__(16) float g_att_enc[B_ * P_ * A_];   // [B*P, A] fp32
__device__ __align__(16) float g_att_h [B_ * A_];
__device__ __align__(16) float g_scores[B_ * P_];
__device__ __align__(16) float g_alpha [B_ * P_];
__device__ __align__(16) float g_weighted[B_ * ENC_];
__device__ __align__(16) float g_sh   [B_ * H_];
__device__ __align__(16) float g_gate [B_ * ENC_];
__device__ __align__(16) float g_gates[B_ * GH_];
__device__ __align__(16) float g_h    [B_ * H_];
__device__ __align__(16) float g_c    [B_ * H_];
__device__ __align__(16) float g_mean [B_ * ENC_];
__device__ __align__(16) float g_bcat [GH_];
__device__ __align__(16) float g_hall [MPRED * H_];       // h for all 19 steps
__device__ int g_tok64;

// bf16 split operands (hi + lo error-compensated)
__device__ __align__(16) __nv_bfloat16 g_enc_hi [B_ * P_ * ENC_];
__device__ __align__(16) __nv_bfloat16 g_enc_lo [B_ * P_ * ENC_];
__device__ __align__(16) __nv_bfloat16 g_We_hi  [A_ * ENC_];
__device__ __align__(16) __nv_bfloat16 g_We_lo  [A_ * ENC_];
__device__ __align__(16) __nv_bfloat16 g_Wfc_hi [V_ * H_];
__device__ __align__(16) __nv_bfloat16 g_Wfc_lo [V_ * H_];
__device__ __align__(16) __nv_bfloat16 g_Wcat_hi[GH_ * KCAT];
__device__ __align__(16) __nv_bfloat16 g_Wcat_lo[GH_ * KCAT];
__device__ __align__(16) __nv_bfloat16 g_inp_hi [B_ * KCAT];
__device__ __align__(16) __nv_bfloat16 g_inp_lo [B_ * KCAT];
__device__ __align__(16) __nv_bfloat16 g_hall_hi[MPRED * H_];
__device__ __align__(16) __nv_bfloat16 g_hall_lo[MPRED * H_];

__device__ __forceinline__ float sigf(float x) { return 1.f / (1.f + __expf(-x)); }

// ================= bf16 tensor-core GEMM: C[M,N] = A[M,K] * B[N,K]^T ==========
// A,B given as (hi, lo) bf16 splits; computes hi*hi + hi*lo + lo*hi in fp32.
// Requirements: M % 64 == 0, K % 32 == 0. N guarded.
// mode 0: C[m*ldc+n] = acc + bias[n]          (grid: x=N-tiles, y=M-tiles)
// mode 1: atomicAdd(C[m*ldc+n], acc)          (split-K via z; bias pre-init)
// mode 2: pred scatter: row m=(t*64+b) -> C[b*T*V + t*V + n] = acc + bias[n]
//         (grid: x=M-tiles, y=N-tiles)
#define LDSM_ 40   // padded smem stride in bf16 (80B, 16B-aligned, conflict-free)

__device__ __forceinline__ void ldsm4(uint32_t* r, uint32_t addr)
{
    asm volatile("ldmatrix.sync.aligned.m8n8.x4.shared.b16 {%0,%1,%2,%3}, [%4];"
                 : "=r"(r[0]), "=r"(r[1]), "=r"(r[2]), "=r"(r[3]) : "r"(addr));
}

__device__ __forceinline__ void mma16816(float* c, const uint32_t* a, uint32_t b0, uint32_t b1)
{
    asm volatile("mma.sync.aligned.m16n8k16.row.col.f32.bf16.bf16.f32 "
                 "{%0,%1,%2,%3}, {%4,%5,%6,%7}, {%8,%9}, {%0,%1,%2,%3};"
                 : "+f"(c[0]), "+f"(c[1]), "+f"(c[2]), "+f"(c[3])
                 : "r"(a[0]), "r"(a[1]), "r"(a[2]), "r"(a[3]), "r"(b0), "r"(b1));
}

__global__ __launch_bounds__(256)
void mma_gemm_kernel(const __nv_bfloat16* __restrict__ Ahi, const __nv_bfloat16* __restrict__ Alo,
                     const __nv_bfloat16* __restrict__ Bhi, const __nv_bfloat16* __restrict__ Blo,
                     float* __restrict__ C, const float* __restrict__ bias,
                     int M, int N, int K, int ldc, int kchunk, int mode)
{
    __shared__ __nv_bfloat16 sAh[64 * LDSM_], sAl[64 * LDSM_];
    __shared__ __nv_bfloat16 sBh[64 * LDSM_], sBl[64 * LDSM_];

    const int tid  = threadIdx.x;
    const int lane = tid & 31;
    const int warp = tid >> 5;
    const int wm = (warp & 1) * 32;    // warp m offset in tile
    const int wn = (warp >> 1) * 16;   // warp n offset in tile

    int m0, n0;
    if (mode == 2) { m0 = blockIdx.x * 64; n0 = blockIdx.y * 64; }
    else           { n0 = blockIdx.x * 64; m0 = blockIdx.y * 64; }

    const int kbeg = blockIdx.z * kchunk;
    const int kend = kbeg + kchunk;

    float acc[2][2][4];
#pragma unroll
    for (int i = 0; i < 2; ++i)
#pragma unroll
        for (int j = 0; j < 2; ++j)
#pragma unroll
            for (int q = 0; q < 4; ++q) acc[i][j][q] = 0.f;

    // global loader mapping: ALL 256 threads cover the full 64x32 tile.
    // lrow 0..63, lchunk in {0,8,16,24} bf16  -> 64*32 = 2048 bf16 per array.
    const int lrow   = tid >> 2;
    const int lchunk = (tid & 3) << 3;

    // smem u32 bases
    const uint32_t sAh_b = (uint32_t)__cvta_generic_to_shared(sAh);
    const uint32_t sAl_b = (uint32_t)__cvta_generic_to_shared(sAl);
    const uint32_t sBh_b = (uint32_t)__cvta_generic_to_shared(sBh);
    const uint32_t sBl_b = (uint32_t)__cvta_generic_to_shared(sBl);

    // per-lane ldmatrix offsets (bf16 units, before *2 bytes)
    const int fr   = lane & 15;            // fragment row
    const int fcof = (lane >> 4) << 3;     // 0 or 8 (k sub-col)
    const int aoff0 = (wm +  0 + fr) * LDSM_ + fcof;
    const int aoff1 = (wm + 16 + fr) * LDSM_ + fcof;
    const int boff  = (wn +       fr) * LDSM_ + fcof;

    for (int k0 = kbeg; k0 < kend; k0 += 32) {
        {
            // A tile (M always multiple of 64 for our call sites)
            size_t gofs = (size_t)(m0 + lrow) * K + k0 + lchunk;
            *(uint4*)&sAh[lrow * LDSM_ + lchunk] = *(const uint4*)(Ahi + gofs);
            *(uint4*)&sAl[lrow * LDSM_ + lchunk] = *(const uint4*)(Alo + gofs);
        }
        {
            // B tile (guarded on N)
            uint4 vh = make_uint4(0u, 0u, 0u, 0u), vl = vh;
            int n = n0 + lrow;
            if (n < N) {
                size_t gofs = (size_t)n * K + k0 + lchunk;
                vh = *(const uint4*)(Bhi + gofs);
                vl = *(const uint4*)(Blo + gofs);
            }
            *(uint4*)&sBh[lrow * LDSM_ + lchunk] = vh;
            *(uint4*)&sBl[lrow * LDSM_ + lchunk] = vl;
        }
        __syncthreads();

#pragma unroll
        for (int kk = 0; kk < 32; kk += 16) {
            uint32_t ah0[4], ah1[4], al0[4], al1[4], bh[4], bl[4];
            ldsm4(ah0, sAh_b + (uint32_t)(aoff0 + kk) * 2);
            ldsm4(ah1, sAh_b + (uint32_t)(aoff1 + kk) * 2);
            ldsm4(al0, sAl_b + (uint32_t)(aoff0 + kk) * 2);
            ldsm4(al1, sAl_b + (uint32_t)(aoff1 + kk) * 2);
            ldsm4(bh,  sBh_b + (uint32_t)(boff  + kk) * 2);
            ldsm4(bl,  sBl_b + (uint32_t)(boff  + kk) * 2);
            // b regs: n-tile0 -> {r0,r2}, n-tile1 -> {r1,r3}
            // hi*hi
            mma16816(acc[0][0], ah0, bh[0], bh[2]);
            mma16816(acc[0][1], ah0, bh[1], bh[3]);
            mma16816(acc[1][0], ah1, bh[0], bh[2]);
            mma16816(acc[1][1], ah1, bh[1], bh[3]);
            // hi*lo
            mma16816(acc[0][0], ah0, bl[0], bl[2]);
            mma16816(acc[0][1], ah0, bl[1], bl[3]);
            mma16816(acc[1][0], ah1, bl[0], bl[2]);
            mma16816(acc[1][1], ah1, bl[1], bl[3]);
            // lo*hi
            mma16816(acc[0][0], al0, bh[0], bh[2]);
            mma16816(acc[0][1], al0, bh[1], bh[3]);
            mma16816(acc[1][0], al1, bh[0], bh[2]);
            mma16816(acc[1][1], al1, bh[1], bh[3]);
        }
        __syncthreads();
    }

    // epilogue
#pragma unroll
    for (int mt = 0; mt < 2; ++mt) {
#pragma unroll
        for (int nt = 0; nt < 2; ++nt) {
            int row = m0 + wm + mt * 16 + (lane >> 2);
            int col = n0 + wn + nt * 8 + ((lane & 3) << 1);
            const float* a = acc[mt][nt];
#pragma unroll
            for (int hh = 0; hh < 2; ++hh) {
                int rr = row + hh * 8;
                float v0 = a[hh * 2 + 0], v1 = a[hh * 2 + 1];
                if (mode == 0) {
                    if (col < N)     C[(size_t)rr * ldc + col]     = v0 + (bias ? bias[col]     : 0.f);
                    if (col + 1 < N) C[(size_t)rr * ldc + col + 1] = v1 + (bias ? bias[col + 1] : 0.f);
                } else if (mode == 1) {
                    if (col < N)     atomicAdd(&C[(size_t)rr * ldc + col],     v0);
                    if (col + 1 < N) atomicAdd(&C[(size_t)rr * ldc + col + 1], v1);
                } else {
                    int tt = rr >> 6, bb = rr & 63;
                    size_t o = (size_t)bb * T_ * V_ + (size_t)tt * V_;
                    if (col < N)     C[o + col]     = v0 + bias[col];
                    if (col + 1 < N) C[o + col + 1] = v1 + bias[col + 1];
                }
            }
        }
    }
}

// ---------------- fp32 SIMT SGEMM (small GEMMs only): C = A[M,K]*B[N,K]^T -----
#define BM 64
#define BN 64
#define BK 16

__global__ __launch_bounds__(256)
void sgemm_kernel(const float* __restrict__ Amat, const float* __restrict__ Bmat,
                  float* __restrict__ C, const float* __restrict__ bias,
                  int M, int N, int K, int ldc, int kchunk, int mode)
{
    __shared__ float As[BK][BM + 4];
    __shared__ float Bs[BK][BN + 4];

    const int tid = threadIdx.x;
    const int tx = tid & 15;
    const int ty = tid >> 4;
    const int m0 = blockIdx.y * BM;
    const int n0 = blockIdx.x * BN;
    const int kbeg = blockIdx.z * kchunk;
    const int kend = kbeg + kchunk;
    const int lr = tid >> 2;
    const int lc = (tid & 3) << 2;

    float acc[4][4] = {};

    for (int k0 = kbeg; k0 < kend; k0 += BK) {
        float4 a4 = make_float4(0.f, 0.f, 0.f, 0.f);
        int am = m0 + lr;
        if (am < M) a4 = *(const float4*)(Amat + (size_t)am * K + k0 + lc);
        As[lc + 0][lr] = a4.x; As[lc + 1][lr] = a4.y;
        As[lc + 2][lr] = a4.z; As[lc + 3][lr] = a4.w;

        float4 b4 = make_float4(0.f, 0.f, 0.f, 0.f);
        int bn = n0 + lr;
        if (bn < N) b4 = *(const float4*)(Bmat + (size_t)bn * K + k0 + lc);
        Bs[lc + 0][lr] = b4.x; Bs[lc + 1][lr] = b4.y;
        Bs[lc + 2][lr] = b4.z; Bs[lc + 3][lr] = b4.w;

        __syncthreads();
#pragma unroll
        for (int k = 0; k < BK; ++k) {
            float4 ra = *(const float4*)&As[k][ty << 2];
            float4 rb = *(const float4*)&Bs[k][tx << 2];
            acc[0][0] += ra.x * rb.x; acc[0][1] += ra.x * rb.y;
            acc[0][2] += ra.x * rb.z; acc[0][3] += ra.x * rb.w;
            acc[1][0] += ra.y * rb.x; acc[1][1] += ra.y * rb.y;
            acc[1][2] += ra.y * rb.z; acc[1][3] += ra.y * rb.w;
            acc[2][0] += ra.z * rb.x; acc[2][1] += ra.z * rb.y;
            acc[2][2] += ra.z * rb.z; acc[2][3] += ra.z * rb.w;
            acc[3][0] += ra.w * rb.x; acc[3][1] += ra.w * rb.y;
            acc[3][2] += ra.w * rb.z; acc[3][3] += ra.w * rb.w;
        }
        __syncthreads();
    }

#pragma unroll
    for (int i = 0; i < 4; ++i) {
        int m = m0 + (ty << 2) + i;
        if (m >= M) continue;
#pragma unroll
        for (int j = 0; j < 4; ++j) {
            int n = n0 + (tx << 2) + j;
            if (n >= N) continue;
            if (mode == 0) C[(size_t)m * ldc + n] = acc[i][j] + (bias ? bias[n] : 0.f);
            else           atomicAdd(&C[(size_t)m * ldc + n], acc[i][j]);
        }
    }
}

// ---------------- small custom kernels ----------------

__global__ __launch_bounds__(256)
void split_kernel(const float* __restrict__ src, __nv_bfloat16* __restrict__ hi,
                  __nv_bfloat16* __restrict__ lo, int n)
{
    int i = blockIdx.x * blockDim.x + threadIdx.x;
    if (i >= n) return;
    float x = src[i];
    __nv_bfloat16 h = __float2bfloat16_rn(x);
    hi[i] = h;
    lo[i] = __float2bfloat16_rn(x - __bfloat162float(h));
}

__global__ __launch_bounds__(256) void detect_tok_kernel(const int* __restrict__ cap32)
{
    __shared__ int bad;
    if (threadIdx.x == 0) bad = 0;
    __syncthreads();
    for (int i = 2 * threadIdx.x + 1; i < B_ * T_; i += 2 * blockDim.x)
        if (cap32[i] != 0) bad = 1;
    __syncthreads();
    if (threadIdx.x == 0) g_tok64 = bad ? 0 : 1;
}

__global__ __launch_bounds__(256) void zero_last_kernel(float* __restrict__ out)
{
    int idx = blockIdx.x * blockDim.x + threadIdx.x;
    if (idx >= B_ * V_) return;
    int b = idx / V_, v = idx % V_;
    out[(size_t)b * T_ * V_ + (size_t)(T_ - 1) * V_ + v] = 0.f;
}

__global__ __launch_bounds__(256) void mean_enc_kernel(const float* __restrict__ enc)
{
    int b = blockIdx.y;
    int e = blockIdx.x * 256 + threadIdx.x;
    float s = 0.f;
    const float* base = enc + (size_t)b * P_ * ENC_ + e;
    for (int p = 0; p < P_; ++p) s += base[(size_t)p * ENC_];
    g_mean[b * ENC_ + e] = s * (1.f / (float)P_);
}

// fused weight [W_ih | W_hh] -> bf16 splits; bias sum
__global__ __launch_bounds__(256)
void build_wcat_split_kernel(const float* __restrict__ W_ih, const float* __restrict__ W_hh,
                             const float* __restrict__ b_ih, const float* __restrict__ b_hh)
{
    int idx = blockIdx.x * blockDim.x + threadIdx.x;
    if (idx < GH_) g_bcat[idx] = b_ih[idx] + b_hh[idx];
    if (idx >= GH_ * KCAT) return;
    int n = idx / KCAT, j = idx % KCAT;
    float w = (j < E_ + ENC_) ? W_ih[(size_t)n * (E_ + ENC_) + j]
                              : W_hh[(size_t)n * H_ + (j - E_ - ENC_)];
    __nv_bfloat16 h = __float2bfloat16_rn(w);
    g_Wcat_hi[idx] = h;
    g_Wcat_lo[idx] = __float2bfloat16_rn(w - __bfloat162float(h));
}

__global__ __launch_bounds__(256)
void init_h0c0_kernel(const float* __restrict__ bch, const float* __restrict__ bcc)
{
    int idx = blockIdx.x * blockDim.x + threadIdx.x;
    if (idx >= B_ * H_) return;
    int n = idx % H_;
    g_h[idx] = bch[n];
    g_c[idx] = bcc[n];
}

__global__ __launch_bounds__(256) void sh0_kernel()
{
    int idx = blockIdx.x * blockDim.x + threadIdx.x;
    if (idx < B_ * H_) g_sh[idx] = sigf(g_h[idx]);
}

__global__ __launch_bounds__(256)
void init3_kernel(const float* __restrict__ bh, const float* __restrict__ bg)
{
    int idx = blockIdx.x * blockDim.x + threadIdx.x;
    if (idx < B_ * A_) g_att_h[idx] = bh[idx % A_];
    int i2 = idx - B_ * A_;
    if (i2 >= 0 && i2 < B_ * ENC_) g_gate[i2] = bg[i2 % ENC_];
    int i3 = idx - B_ * A_ - B_ * ENC_;
    if (i3 >= 0 && i3 < B_ * GH_) g_gates[i3] = g_bcat[i3 % GH_];
}

__global__ __launch_bounds__(256)
void scores_kernel(const float* __restrict__ Wa, const float* __restrict__ ba)
{
    __shared__ float s_h[A_];
    __shared__ float s_w[A_];
    int b = blockIdx.y;
    for (int i = threadIdx.x; i < A_; i += 256) {
        s_h[i] = g_att_h[b * A_ + i];
        s_w[i] = Wa[i];
    }
    __syncthreads();
    int w = threadIdx.x >> 5, lane = threadIdx.x & 31;
    int p = blockIdx.x * 8 + w;
    if (p >= P_) return;
    const float* row = g_att_enc + ((size_t)(b * P_ + p)) * A_;
    float s = 0.f;
    for (int a = lane; a < A_; a += 32) {
        float v = row[a] + s_h[a];
        s += fmaxf(v, 0.f) * s_w[a];
    }
#pragma unroll
    for (int o = 16; o; o >>= 1) s += __shfl_xor_sync(0xffffffff, s, o);
    if (lane == 0) g_scores[b * P_ + p] = s + ba[0];
}

__global__ __launch_bounds__(256) void softmax_kernel()
{
    __shared__ float red[256];
    int b = blockIdx.x, t = threadIdx.x;
    float v = (t < P_) ? g_scores[b * P_ + t] : -1e30f;
    red[t] = v; __syncthreads();
    for (int s = 128; s; s >>= 1) { if (t < s) red[t] = fmaxf(red[t], red[t + s]); __syncthreads(); }
    float mx = red[0]; __syncthreads();
    float e = (t < P_) ? __expf(v - mx) : 0.f;
    red[t] = e; __syncthreads();
    for (int s = 128; s; s >>= 1) { if (t < s) red[t] += red[t + s]; __syncthreads(); }
    float inv = 1.f / red[0];
    if (t < P_) g_alpha[b * P_ + t] = e * inv;
}

__global__ __launch_bounds__(256) void weighted_kernel(const float* __restrict__ enc)
{
    __shared__ float sa[P_];
    int b = blockIdx.y;
    int e = blockIdx.x * 256 + threadIdx.x;
    for (int i = threadIdx.x; i < P_; i += 256) sa[i] = g_alpha[b * P_ + i];
    __syncthreads();
    const float* base = enc + (size_t)b * P_ * ENC_ + e;
    float s = 0.f;
    for (int p = 0; p < P_; ++p) s += sa[p] * base[(size_t)p * ENC_];
    g_weighted[b * ENC_ + e] = s;
}

// inp = [x_t, weighted*gate, h] -> bf16 splits directly
__global__ __launch_bounds__(256)
void build_inp_split_kernel(const void* __restrict__ cap, const float* __restrict__ emb, int t)
{
    int idx = blockIdx.x * blockDim.x + threadIdx.x;
    if (idx >= B_ * KCAT) return;
    int b = idx / KCAT, j = idx % KCAT;
    float v;
    if (j < E_) {
        long long tok = g_tok64 ? ((const long long*)cap)[b * T_ + t]
                                : (long long)((const int*)cap)[b * T_ + t];
        v = emb[(size_t)tok * E_ + j];
    } else if (j < E_ + ENC_) {
        int e = j - E_;
        v = g_weighted[b * ENC_ + e] * g_gate[b * ENC_ + e];
    } else {
        v = g_h[b * H_ + (j - E_ - ENC_)];
    }
    __nv_bfloat16 h = __float2bfloat16_rn(v);
    g_inp_hi[idx] = h;
    g_inp_lo[idx] = __float2bfloat16_rn(v - __bfloat162float(h));
}

// LSTM pointwise: update c,h, emit sigmoid(h), record h into g_hall[t]
__global__ __launch_bounds__(256) void lstm_kernel(int t)
{
    int idx = blockIdx.x * blockDim.x + threadIdx.x;
    if (idx >= B_ * H_) return;
    int b = idx / H_, j = idx % H_;
    const float* g = g_gates + (size_t)b * GH_;
    float i_ = sigf(g[j]);
    float f_ = sigf(g[H_ + j]);
    float gg = tanhf(g[2 * H_ + j]);
    float o_ = sigf(g[3 * H_ + j]);
    float c = f_ * g_c[idx] + i_ * gg;
    float h = o_ * tanhf(c);
    g_c[idx] = c;
    g_h[idx] = h;
    g_sh[idx] = sigf(h);
    g_hall[(size_t)t * B_ * H_ + idx] = h;
}

// ---------------- host orchestration ----------------
static inline float* symf(const void* s)
{
    void* p = nullptr;
    cudaGetSymbolAddress(&p, s);
    return (float*)p;
}
static inline __nv_bfloat16* symb(const void* s)
{
    void* p = nullptr;
    cudaGetSymbolAddress(&p, s);
    return (__nv_bfloat16*)p;
}

extern "C" void kernel_launch(void* const* d_in, const int* in_sizes, int n_in,
                              void* d_out, int out_size)
{
    const float* encode_out = (const float*)d_in[0];
    const void*  captions   = d_in[1];
    const float* emb        = (const float*)d_in[2];
    const float* W_ih       = (const float*)d_in[3];
    const float* b_ih       = (const float*)d_in[4];
    const float* W_hh       = (const float*)d_in[5];
    const float* b_hh       = (const float*)d_in[6];
    const float* We         = (const float*)d_in[7];
    const float* be         = (const float*)d_in[8];
    const float* Wh         = (const float*)d_in[9];
    const float* bh         = (const float*)d_in[10];
    const float* Wa         = (const float*)d_in[11];
    const float* ba         = (const float*)d_in[12];
    const float* Wch        = (const float*)d_in[13];
    const float* bch        = (const float*)d_in[14];
    const float* Wcc        = (const float*)d_in[15];
    const float* bcc        = (const float*)d_in[16];
    const float* Wfc        = (const float*)d_in[17];
    const float* bfc        = (const float*)d_in[18];
    const float* Wg         = (const float*)d_in[19];
    const float* bg         = (const float*)d_in[20];
    float* out = (float*)d_out;

    float* p_att_enc = symf(g_att_enc);
    float* p_att_h   = symf(g_att_h);
    float* p_sh      = symf(g_sh);
    float* p_gate    = symf(g_gate);
    float* p_gates   = symf(g_gates);
    float* p_h       = symf(g_h);
    float* p_c       = symf(g_c);
    float* p_mean    = symf(g_mean);
    float* p_hall    = symf(g_hall);

    __nv_bfloat16* p_enc_hi  = symb(g_enc_hi);
    __nv_bfloat16* p_enc_lo  = symb(g_enc_lo);
    __nv_bfloat16* p_We_hi   = symb(g_We_hi);
    __nv_bfloat16* p_We_lo   = symb(g_We_lo);
    __nv_bfloat16* p_Wfc_hi  = symb(g_Wfc_hi);
    __nv_bfloat16* p_Wfc_lo  = symb(g_Wfc_lo);
    __nv_bfloat16* p_Wcat_hi = symb(g_Wcat_hi);
    __nv_bfloat16* p_Wcat_lo = symb(g_Wcat_lo);
    __nv_bfloat16* p_inp_hi  = symb(g_inp_hi);
    __nv_bfloat16* p_inp_lo  = symb(g_inp_lo);
    __nv_bfloat16* p_hall_hi = symb(g_hall_hi);
    __nv_bfloat16* p_hall_lo = symb(g_hall_lo);

    // ---- prologue ----
    detect_tok_kernel<<<1, 256>>>((const int*)captions);
    zero_last_kernel<<<(B_ * V_ + 255) / 256, 256>>>(out);
    mean_enc_kernel<<<dim3(ENC_ / 256, B_), 256>>>(encode_out);

    split_kernel<<<(B_ * P_ * ENC_ + 255) / 256, 256>>>(encode_out, p_enc_hi, p_enc_lo, B_ * P_ * ENC_);
    split_kernel<<<(A_ * ENC_ + 255) / 256, 256>>>(We, p_We_hi, p_We_lo, A_ * ENC_);
    split_kernel<<<(V_ * H_ + 255) / 256, 256>>>(Wfc, p_Wfc_hi, p_Wfc_lo, V_ * H_);
    build_wcat_split_kernel<<<(GH_ * KCAT + 255) / 256, 256>>>(W_ih, W_hh, b_ih, b_hh);

    init_h0c0_kernel<<<(B_ * H_ + 255) / 256, 256>>>(bch, bcc);
    sgemm_kernel<<<dim3(H_ / BN, 1, 8), 256>>>(p_mean, Wch, p_h, nullptr,
                                               B_, H_, ENC_, H_, ENC_ / 8, 1);
    sgemm_kernel<<<dim3(H_ / BN, 1, 8), 256>>>(p_mean, Wcc, p_c, nullptr,
                                               B_, H_, ENC_, H_, ENC_ / 8, 1);
    sh0_kernel<<<(B_ * H_ + 255) / 256, 256>>>();

    // att_enc = encode_out @ We^T + be   (bf16-split tensor-core GEMM)
    mma_gemm_kernel<<<dim3(A_ / 64, (B_ * P_) / 64, 1), 256>>>(
        p_enc_hi, p_enc_lo, p_We_hi, p_We_lo, p_att_enc, be,
        B_ * P_, A_, ENC_, A_, ENC_, 0);

    const int INIT3_N = B_ * A_ + B_ * ENC_ + B_ * GH_;

    // ---- timesteps ----
    for (int t = 0; t < T_ - 1; ++t) {
        init3_kernel<<<(INIT3_N + 255) / 256, 256>>>(bh, bg);
        sgemm_kernel<<<dim3(A_ / BN, 1, 8), 256>>>(p_h, Wh, p_att_h, nullptr,
                                                   B_, A_, H_, A_, H_ / 8, 1);
        scores_kernel<<<dim3((P_ + 7) / 8, B_), 256>>>(Wa, ba);
        softmax_kernel<<<B_, 256>>>();
        weighted_kernel<<<dim3(ENC_ / 256, B_), 256>>>(encode_out);
        sgemm_kernel<<<dim3(ENC_ / BN, 1, 4), 256>>>(p_sh, Wg, p_gate, nullptr,
                                                     B_, ENC_, H_, ENC_, H_ / 4, 1);
        build_inp_split_kernel<<<(B_ * KCAT + 255) / 256, 256>>>(captions, emb, t);
        // gates = inp @ Wcat^T + (b_ih+b_hh)  (tensor-core, split-K 8, atomic)
        mma_gemm_kernel<<<dim3(GH_ / 64, 1, 8), 256>>>(
            p_inp_hi, p_inp_lo, p_Wcat_hi, p_Wcat_lo, p_gates, nullptr,
            B_, GH_, KCAT, GH_, KCAT / 8, 1);
        lstm_kernel<<<(B_ * H_ + 255) / 256, 256>>>(t);
    }

    // ---- batched pred: out[b,t,:] = h_all[t,b,:] @ Wfc^T + bfc ----
    split_kernel<<<(MPRED * H_ + 255) / 256, 256>>>(p_hall, p_hall_hi, p_hall_lo, MPRED * H_);
    mma_gemm_kernel<<<dim3(MPRED / 64, (V_ + 63) / 64, 1), 256>>>(
        p_hall_hi, p_hall_lo, p_Wfc_hi, p_Wfc_lo, out, bfc,
        MPRED, V_, H_, 0 /*ldc unused*/, H_, 2);
}